// round 2
// baseline (speedup 1.0000x reference)
#include <cuda_runtime.h>
#include <math.h>

#define B_SZ  32
#define T_LEN 2048
#define I_DIM 128
#define H_DIM 256
#define N_TOK (B_SZ * T_LEN)   // 65536

// Scratch (device globals: allocation-free rule)
__device__ float g_xB[(size_t)N_TOK * H_DIM];   // 64 MB
__device__ float g_hs[(size_t)N_TOK * H_DIM];   // 64 MB

// ---------------------------------------------------------------------------
// Generic fp32 tiled GEMM: Y[M,N] = X[M,K] @ W[K,N]
// BM=128, BN=64, BK=16, 256 threads, 8x4 micro-tile per thread.
// Requires M%128==0, N%64==0, K%16==0 (true for all uses here).
// ---------------------------------------------------------------------------
__global__ void __launch_bounds__(256) gemm_kernel(const float* __restrict__ X,
                                                   const float* __restrict__ W,
                                                   float* __restrict__ Y,
                                                   int M, int K, int N) {
    __shared__ float Xs[16][128];
    __shared__ float Ws[16][64];

    const int tid = threadIdx.x;
    const int m0 = blockIdx.x * 128;
    const int n0 = blockIdx.y * 64;
    const int tx = tid & 15;     // 0..15 -> 4 cols
    const int ty = tid >> 4;     // 0..15 -> 8 rows

    float acc[8][4];
#pragma unroll
    for (int r = 0; r < 8; r++)
#pragma unroll
        for (int cc = 0; cc < 4; cc++) acc[r][cc] = 0.f;

    const int lrow  = tid >> 1;          // 0..127
    const int lpart = (tid & 1) * 8;     // 0 or 8

    for (int kt = 0; kt < K; kt += 16) {
        // Load X tile [128 x 16], store transposed into Xs[k][row]
        const float* xp = X + (size_t)(m0 + lrow) * K + kt + lpart;
        float4 v0 = *(const float4*)(xp);
        float4 v1 = *(const float4*)(xp + 4);
        Xs[lpart + 0][lrow] = v0.x;
        Xs[lpart + 1][lrow] = v0.y;
        Xs[lpart + 2][lrow] = v0.z;
        Xs[lpart + 3][lrow] = v0.w;
        Xs[lpart + 4][lrow] = v1.x;
        Xs[lpart + 5][lrow] = v1.y;
        Xs[lpart + 6][lrow] = v1.z;
        Xs[lpart + 7][lrow] = v1.w;

        // Load W tile [16 x 64]
        {
            const int wk = tid >> 4;           // 0..15
            const int wn = (tid & 15) * 4;     // 0..60
            float4 wv = *(const float4*)(W + (size_t)(kt + wk) * N + n0 + wn);
            *(float4*)&Ws[wk][wn] = wv;
        }
        __syncthreads();

#pragma unroll
        for (int k = 0; k < 16; k++) {
            float4 xa = *(const float4*)&Xs[k][ty * 8];
            float4 xb = *(const float4*)&Xs[k][ty * 8 + 4];
            float4 wv = *(const float4*)&Ws[k][tx * 4];
            float xr[8] = {xa.x, xa.y, xa.z, xa.w, xb.x, xb.y, xb.z, xb.w};
            float wr[4] = {wv.x, wv.y, wv.z, wv.w};
#pragma unroll
            for (int r = 0; r < 8; r++)
#pragma unroll
                for (int cc = 0; cc < 4; cc++)
                    acc[r][cc] = fmaf(xr[r], wr[cc], acc[r][cc]);
        }
        __syncthreads();
    }

#pragma unroll
    for (int r = 0; r < 8; r++) {
        float4 o = make_float4(acc[r][0], acc[r][1], acc[r][2], acc[r][3]);
        *(float4*)&Y[(size_t)(m0 + ty * 8 + r) * N + n0 + tx * 4] = o;
    }
}

// ---------------------------------------------------------------------------
// Scan kernel: one CTA per batch row. 512 threads.
// Thread (j = tid>>1, c = tid&1) computes the partial dot for output column j
// over rows [c*128, c*128+128): 96 rows with A in registers, 32 rows with A
// re-read from smem each step. h double-buffered in smem with a 16B skew
// between halves so c=0/c=1 reads hit disjoint bank groups.
// ---------------------------------------------------------------------------
__global__ void __launch_bounds__(512, 1) scan_kernel(const float* __restrict__ A) {
    extern __shared__ float smem[];
    float* As3  = smem;                 // [512][36]  (padded rows, 73728 B)
    float* sh_h = smem + 512 * 36;      // [2][264]   (double-buffered h, padded)
    const int HB = 264;

    const int tid = threadIdx.x;
    const int b   = blockIdx.x;
    const int j   = tid >> 1;   // 0..255
    const int c   = tid & 1;    // 0..1

    // A column chunk into registers: rows c*128 + (0..95), column j
    float a[96];
    {
        const float* Ac = A + (size_t)(c * 128) * H_DIM + j;
#pragma unroll
        for (int k = 0; k < 96; k++) a[k] = Ac[(size_t)k * H_DIM];
    }
    // A tail rows c*128 + 96 + (0..31) into smem (per-thread slot, stride 36)
    {
        float* mine = As3 + tid * 36;
        const float* Ac = A + (size_t)(c * 128 + 96) * H_DIM + j;
#pragma unroll
        for (int r = 0; r < 32; r++) mine[r] = Ac[(size_t)r * H_DIM];
    }
    // h0 = 0 (padded layout: index j -> j + (j>=128 ? 4 : 0))
    if (tid < H_DIM) sh_h[tid + ((tid >= 128) ? 4 : 0)] = 0.f;
    __syncthreads();

    const float* xB = g_xB + (size_t)b * T_LEN * H_DIM;
    float*       hs = g_hs + (size_t)b * T_LEN * H_DIM;
    const float4* As4 = (const float4*)(As3 + tid * 36);  // 8 float4

    float xb_next = xB[j];   // prefetch step 0
    int cur = 0;

    for (int step = 0; step < T_LEN; step++) {
        const float xb = xb_next;
        const int nstep = (step + 1 < T_LEN) ? (step + 1) : step;
        xb_next = xB[(size_t)nstep * H_DIM + j];

        const float4* hp4 = (const float4*)(sh_h + cur * HB) + c * 33;

        float a0 = 0.f, a1 = 0.f;
#pragma unroll
        for (int q = 0; q < 24; q++) {
            float4 hv = hp4[q];
            a0 = fmaf(hv.x, a[q * 4 + 0], a0);
            a1 = fmaf(hv.y, a[q * 4 + 1], a1);
            a0 = fmaf(hv.z, a[q * 4 + 2], a0);
            a1 = fmaf(hv.w, a[q * 4 + 3], a1);
        }
#pragma unroll
        for (int q = 0; q < 8; q++) {
            float4 hv = hp4[24 + q];
            float4 av = As4[q];
            a0 = fmaf(hv.x, av.x, a0);
            a1 = fmaf(hv.y, av.y, a1);
            a0 = fmaf(hv.z, av.z, a0);
            a1 = fmaf(hv.w, av.w, a1);
        }
        float acc = a0 + a1;
        acc += __shfl_xor_sync(0xffffffffu, acc, 1);   // combine c=0 / c=1

        if (c == 0) {
            float y = tanhf(acc + xb);
            sh_h[(cur ^ 1) * HB + j + ((j >= 128) ? 4 : 0)] = y;
        }
        __syncthreads();

        // stream h_t to global (coalesced 1 KB)
        if (tid < H_DIM)
            hs[(size_t)step * H_DIM + tid] =
                sh_h[(cur ^ 1) * HB + tid + ((tid >= 128) ? 4 : 0)];
        cur ^= 1;
    }
}

// ---------------------------------------------------------------------------
extern "C" void kernel_launch(void* const* d_in, const int* in_sizes, int n_in,
                              void* d_out, int out_size) {
    const float* x  = (const float*)d_in[0];   // [32,2048,128]
    const float* A  = (const float*)d_in[1];   // [256,256]
    const float* Bm = (const float*)d_in[2];   // [128,256]
    const float* C  = (const float*)d_in[3];   // [256,256]
    float* out = (float*)d_out;                // [32,2048,256]

    float* xBp = nullptr;
    float* hsp = nullptr;
    cudaGetSymbolAddress((void**)&xBp, g_xB);
    cudaGetSymbolAddress((void**)&hsp, g_hs);

    const int scan_smem = 512 * 36 * 4 + 2 * 264 * 4;   // 75840 B
    cudaFuncSetAttribute(scan_kernel,
                         cudaFuncAttributeMaxDynamicSharedMemorySize, scan_smem);

    // 1) xB = x @ Bm : [65536,128] @ [128,256]
    gemm_kernel<<<dim3(N_TOK / 128, H_DIM / 64), 256>>>(x, Bm, xBp, N_TOK, I_DIM, H_DIM);
    // 2) sequential scan over T, one CTA per batch
    scan_kernel<<<B_SZ, 512, scan_smem>>>(A);
    // 3) out = hs @ C : [65536,256] @ [256,256]
    gemm_kernel<<<dim3(N_TOK / 128, H_DIM / 64), 256>>>(hsp, C, out, N_TOK, H_DIM, H_DIM);
}